// round 12
// baseline (speedup 1.0000x reference)
#include <cuda_runtime.h>
#include <cuda_bf16.h>
#include <cstdint>

#define N_SRC 8192
#define N_TGT 16384
#define DD 64
#define HH 128
#define KN 32
#define CMAX 256
#define GRID 8
#define NCELL (GRID*GRID*GRID)
#define TPT 4                      // targets per GEMM tile (M = 128)
#define NTILE (N_TGT / TPT)        // 4096 tiles
#define NBLK_G 148                 // persistent GEMM blocks (1/SM)

#define LDA 136                    // bf16 leading dim (conflict-free ldmatrix)

// ---------------- device scratch ----------------
static __device__ float  g_S[N_SRC * HH];
static __device__ float4 g_spos[N_SRC];
static __device__ float  g_ss[N_SRC];
static __device__ int    g_cell[N_SRC];
static __device__ int    g_cnt[NCELL];          // zero-init; reset by k_gemm tail
static __device__ int    g_fill[NCELL];
static __device__ int    g_start[NCELL + 1];
static __device__ float4 g_bp[N_SRC];
static __device__ int    g_bidx[N_SRC];
static __device__ float4 g_nbr[N_TGT * KN];     // (relx, rely, relz, bitcast j or -1)
static __device__ int    g_scnt[N_TGT];

// ---------------- k_gemm smem layout (bytes) ----------------
#define SM_BHI   0                       // 128*136*2 = 34816
#define SM_BLO   34816
#define SM_A0HI  69632                   // buffer 0
#define SM_A0LO  104448
#define SM_A1HI  139264                  // buffer 1
#define SM_A1LO  174080
#define SM_W1    208896                  // 3*128*4 = 1536
#define SM_B2    210432                  // 512
#define SMEM_G   210944

static __device__ __forceinline__ uint32_t smem_u32(const void* p) {
    uint32_t a;
    asm("{ .reg .u64 t; cvta.to.shared.u64 t, %1; cvt.u32.u64 %0, t; }" : "=r"(a) : "l"(p));
    return a;
}

static __device__ __forceinline__ void ldsm_x4(uint32_t* r, uint32_t addr) {
    asm volatile("ldmatrix.sync.aligned.m8n8.x4.shared.b16 {%0,%1,%2,%3}, [%4];"
                 : "=r"(r[0]), "=r"(r[1]), "=r"(r[2]), "=r"(r[3]) : "r"(addr));
}
static __device__ __forceinline__ void ldsm_x2t(uint32_t* r, uint32_t addr) {
    asm volatile("ldmatrix.sync.aligned.m8n8.x2.trans.shared.b16 {%0,%1}, [%2];"
                 : "=r"(r[0]), "=r"(r[1]) : "r"(addr));
}
static __device__ __forceinline__ void mma_bf16(float* d, const uint32_t* a, const uint32_t* b) {
    asm volatile("mma.sync.aligned.m16n8k16.row.col.f32.bf16.bf16.f32 "
                 "{%0,%1,%2,%3}, {%4,%5,%6,%7}, {%8,%9}, {%0,%1,%2,%3};"
                 : "+f"(d[0]), "+f"(d[1]), "+f"(d[2]), "+f"(d[3])
                 : "r"(a[0]), "r"(a[1]), "r"(a[2]), "r"(a[3]), "r"(b[0]), "r"(b[1]));
}

static __device__ __forceinline__ int cell_of(float x, float y, float z) {
    int cx = min(GRID - 1, max(0, (int)floorf(x * (float)GRID)));
    int cy = min(GRID - 1, max(0, (int)floorf(y * (float)GRID)));
    int cz = min(GRID - 1, max(0, (int)floorf(z * (float)GRID)));
    return (cz * GRID + cy) * GRID + cx;
}

// ---------------------------------------------------------------------------
__global__ void __launch_bounds__(128) k_pre(
    const float* __restrict__ srcf, const float* __restrict__ srcp,
    const int* __restrict__ srcb, const float* __restrict__ W1,
    const float* __restrict__ b1)
{
    const int j0 = blockIdx.x * 4;
    const int t = threadIdx.x;
    __shared__ float sx[4][DD];
    for (int i = t; i < 4 * DD; i += 128) sx[i / DD][i % DD] = srcf[j0 * DD + i];
    __syncthreads();
    float a0, a1, a2, a3;
    a0 = a1 = a2 = a3 = b1[t];
#pragma unroll
    for (int d = 0; d < DD; d++) {
        float w = W1[d * HH + t];
        a0 = fmaf(sx[0][d], w, a0);
        a1 = fmaf(sx[1][d], w, a1);
        a2 = fmaf(sx[2][d], w, a2);
        a3 = fmaf(sx[3][d], w, a3);
    }
    g_S[(j0 + 0) * HH + t] = a0;
    g_S[(j0 + 1) * HH + t] = a1;
    g_S[(j0 + 2) * HH + t] = a2;
    g_S[(j0 + 3) * HH + t] = a3;
    if (t < 4) {
        int j = j0 + t;
        float x = srcp[j * 3 + 0], y = srcp[j * 3 + 1], z = srcp[j * 3 + 2];
        g_spos[j] = make_float4(x, y, z, (float)srcb[j]);
        g_ss[j] = x * x + y * y + z * z;
        int c = cell_of(x, y, z);
        g_cell[j] = c;
        atomicAdd(&g_cnt[c], 1);
    }
}

__global__ void __launch_bounds__(NCELL) k_scan() {
    __shared__ int s[NCELL];
    int t = threadIdx.x;
    s[t] = g_cnt[t];
    __syncthreads();
#pragma unroll
    for (int off = 1; off < NCELL; off <<= 1) {
        int v = (t >= off) ? s[t - off] : 0;
        __syncthreads();
        s[t] += v;
        __syncthreads();
    }
    g_start[t + 1] = s[t];
    if (t == 0) g_start[0] = 0;
}

__global__ void __launch_bounds__(128) k_scatter() {
    int j = blockIdx.x * 128 + threadIdx.x;
    if (j >= N_SRC) return;
    int c = g_cell[j];
    int off = atomicAdd(&g_fill[c], 1);
    int dst = g_start[c] + off;
    float4 p = g_spos[j];
    g_bp[dst] = make_float4(p.x, p.y, p.z, g_ss[j]);
    g_bidx[dst] = j;
}

// ---------------------------------------------------------------------------
// search: one block per target; warp-per-span scan + aggregated push
// ---------------------------------------------------------------------------
__global__ void __launch_bounds__(128) k_search(const float* __restrict__ tpos)
{
    __shared__ float cd2[CMAX];
    __shared__ int   cidx[CMAX];
    __shared__ int   ssel[KN];
    __shared__ int   scnt;

    const int t    = blockIdx.x;
    const int tid  = threadIdx.x;
    const int wid  = tid >> 5;
    const int lane = tid & 31;

    const float tx = tpos[t * 3 + 0];
    const float ty = tpos[t * 3 + 1];
    const float tz = tpos[t * 3 + 2];
    const float tt = tx * tx + ty * ty + tz * tz;
    const float R2 = (float)(0.12 * 0.12);

    if (tid == 0) scnt = 0;

    const float RM = 0.121f;
    const int lx = max(0, (int)floorf((tx - RM) * (float)GRID));
    const int hx = min(GRID - 1, (int)floorf((tx + RM) * (float)GRID));
    const int ly = max(0, (int)floorf((ty - RM) * (float)GRID));
    const int hy = min(GRID - 1, (int)floorf((ty + RM) * (float)GRID));
    const int lz = max(0, (int)floorf((tz - RM) * (float)GRID));
    const int hz = min(GRID - 1, (int)floorf((tz + RM) * (float)GRID));
    const int nsy = hy - ly + 1;
    const int ns  = nsy * (hz - lz + 1);
    __syncthreads();               // scnt visible

    for (int sp = wid; sp < ns; sp += 4) {
        const int cz = lz + sp / nsy;
        const int cy = ly + sp % nsy;
        const int cbase = (cz * GRID + cy) * GRID;
        const int s0 = g_start[cbase + lx];
        const int s1 = g_start[cbase + hx + 1];
        for (int s = s0 + lane; s - lane < s1; s += 32) {   // warp-uniform trip
            bool hit = false;
            float d2 = 0.f;
            if (s < s1) {
                float4 p = g_bp[s];
                float dot = tx * p.x + ty * p.y + tz * p.z;
                d2 = (tt + p.w) - 2.0f * dot;
                hit = (d2 <= R2);
            }
            unsigned m = __ballot_sync(0xffffffffu, hit);
            if (m) {
                int leader = __ffs(m) - 1;
                int base = 0;
                if (lane == leader) base = atomicAdd(&scnt, __popc(m));
                base = __shfl_sync(0xffffffffu, base, leader);
                if (hit) {
                    int off = base + __popc(m & ((1u << lane) - 1u));
                    if (off < CMAX) { cd2[off] = d2; cidx[off] = g_bidx[s]; }
                }
            }
        }
    }
    __syncthreads();

    const int C = min(scnt, CMAX);
    const int selCnt = min(C, KN);

    if (C <= KN) {
        if (tid < C) ssel[tid] = cidx[tid];
    } else {
        for (int i = tid; i < C; i += 128) {
            float di = cd2[i];
            int   ii = cidx[i];
            int r = 0;
            for (int k2 = 0; k2 < C; k2++) {
                float dk = cd2[k2];
                r += (int)((dk < di) || (dk == di && cidx[k2] < ii));
            }
            if (r < KN) ssel[r] = cidx[i];
        }
    }
    __syncthreads();

    if (tid < KN) {
        if (tid < selCnt) {
            int j = ssel[tid];
            float4 p = g_spos[j];
            g_nbr[t * KN + tid] = make_float4(p.x - tx, p.y - ty, p.z - tz,
                                              __int_as_float(j));
        } else {
            g_nbr[t * KN + tid] = make_float4(0.f, 0.f, 0.f, __int_as_float(-1));
        }
    }
    if (tid == 0) g_scnt[t] = selCnt;
}

// ---------------------------------------------------------------------------
// A-tile build: h1 split-bf16 for tile g into (dh_base, dl_base).
// 256 threads: row = tid>>1 (0..127), col half = (tid&1)*64.
// ---------------------------------------------------------------------------
static __device__ __forceinline__ void buildA(
    __nv_bfloat16* dh_base, __nv_bfloat16* dl_base,
    int g, int tid, const float* sW1)
{
    const int arow = tid >> 1;
    const int acol = (tid & 1) * 64;
    float4 nb = g_nbr[g * (TPT * KN) + arow];
    int j = __float_as_int(nb.w);
    const float* Srow = g_S + (j >= 0 ? j : 0) * HH + acol;
    __nv_bfloat16* dh = dh_base + arow * LDA + acol;
    __nv_bfloat16* dl = dl_base + arow * LDA + acol;
#pragma unroll 4
    for (int c = 0; c < 64; c += 4) {
        float4 sv = (j >= 0) ? *(const float4*)(Srow + c)
                             : make_float4(0.f, 0.f, 0.f, 0.f);
        float4 wx = *(const float4*)(sW1 + 0 * HH + acol + c);
        float4 wy = *(const float4*)(sW1 + 1 * HH + acol + c);
        float4 wz = *(const float4*)(sW1 + 2 * HH + acol + c);
        float v0 = fmaxf(sv.x + nb.x * wx.x + nb.y * wy.x + nb.z * wz.x, 0.f);
        float v1 = fmaxf(sv.y + nb.x * wx.y + nb.y * wy.y + nb.z * wz.y, 0.f);
        float v2 = fmaxf(sv.z + nb.x * wx.z + nb.y * wy.z + nb.z * wz.z, 0.f);
        float v3 = fmaxf(sv.w + nb.x * wx.w + nb.y * wy.w + nb.z * wz.w, 0.f);
        __nv_bfloat162 h01 = __floats2bfloat162_rn(v0, v1);
        __nv_bfloat162 h23 = __floats2bfloat162_rn(v2, v3);
        __nv_bfloat162 l01 = __floats2bfloat162_rn(v0 - __low2float(h01),
                                                   v1 - __high2float(h01));
        __nv_bfloat162 l23 = __floats2bfloat162_rn(v2 - __low2float(h23),
                                                   v3 - __high2float(h23));
        *(uint2*)(dh + c) = make_uint2(*(uint32_t*)&h01, *(uint32_t*)&h23);
        *(uint2*)(dl + c) = make_uint2(*(uint32_t*)&l01, *(uint32_t*)&l23);
    }
}

// ---------------------------------------------------------------------------
// GEMM: persistent; tile = 4 targets x 32 nbrs (M=128); split-bf16 mma.sync;
// double-buffered A, ONE barrier per tile (build overlaps MMA/epilogue).
// ---------------------------------------------------------------------------
__global__ void __launch_bounds__(256) k_gemm(
    const float* __restrict__ W1, const float* __restrict__ W2g,
    const float* __restrict__ b2, float* __restrict__ out)
{
    extern __shared__ char smg[];
    __nv_bfloat16* sBhi = (__nv_bfloat16*)(smg + SM_BHI);
    __nv_bfloat16* sBlo = (__nv_bfloat16*)(smg + SM_BLO);
    __nv_bfloat16* aH[2] = {(__nv_bfloat16*)(smg + SM_A0HI), (__nv_bfloat16*)(smg + SM_A1HI)};
    __nv_bfloat16* aL[2] = {(__nv_bfloat16*)(smg + SM_A0LO), (__nv_bfloat16*)(smg + SM_A1LO)};
    float*         sW1  = (float*)(smg + SM_W1);      // [3][128]
    float*         sB2  = (float*)(smg + SM_B2);

    const int tid  = threadIdx.x;
    const int wid  = tid >> 5;
    const int lane = tid & 31;

    // ---- stage W2 split-bf16 (row-major [k][n]) + W1 positional rows + b2 ----
    for (int i = tid; i < HH * HH; i += 256) {
        int k = i >> 7, n = i & 127;
        float w = W2g[i];
        __nv_bfloat16 hb = __float2bfloat16(w);
        __nv_bfloat16 lb = __float2bfloat16(w - __bfloat162float(hb));
        sBhi[k * LDA + n] = hb;
        sBlo[k * LDA + n] = lb;
    }
    for (int i = tid; i < 3 * HH; i += 256) sW1[i] = W1[64 * HH + i];
    for (int i = tid; i < HH; i += 256)     sB2[i] = b2[i];
    __syncthreads();

    // warp tiling: 4m x 2n; warp tile 32 rows (1 target) x 64 cols
    const int wm = wid & 3;
    const int wn = wid >> 2;
    const int mA = 32 * wm;
    const int nB = 64 * wn;

    const uint32_t uBhi = smem_u32(sBhi), uBlo = smem_u32(sBlo);
    uint32_t uAH[2] = {smem_u32(aH[0]), smem_u32(aH[1])};
    uint32_t uAL[2] = {smem_u32(aL[0]), smem_u32(aL[1])};

    // per-thread ldmatrix offsets (bytes, relative to buffer base)
    const int l15 = lane & 15;
    uint32_t aoff[2];
#pragma unroll
    for (int mt = 0; mt < 2; mt++)
        aoff[mt] = (uint32_t)(((mA + mt * 16 + l15) * LDA + (lane >> 4) * 8) * 2);
    const uint32_t boff  = (uint32_t)((l15 * LDA + nB) * 2);
    const uint32_t kstep = 16 * LDA * 2;

    // per-thread bias registers (cols fixed across tiles)
    const int tid4 = lane & 3;
    const int g4   = lane >> 2;
    float bias0[8], bias1[8];
#pragma unroll
    for (int nt = 0; nt < 8; nt++) {
        int c = nB + nt * 8 + tid4 * 2;
        bias0[nt] = sB2[c];
        bias1[nt] = sB2[c + 1];
    }

    // ---- prologue: build first tile into buffer 0 ----
    buildA(aH[0], aL[0], blockIdx.x, tid, sW1);
    __syncthreads();

    int p = 0;
    for (int g = blockIdx.x; g < NTILE; g += NBLK_G) {
        const int sc = g_scnt[g * TPT + wm];

        // ---- mma: D = bias + Ah*Bh + Ah*Bl + Al*Bh  (reads buf p) ----
        float d[2][8][4];
#pragma unroll
        for (int mt = 0; mt < 2; mt++)
#pragma unroll
            for (int nt = 0; nt < 8; nt++) {
                d[mt][nt][0] = bias0[nt];
                d[mt][nt][1] = bias1[nt];
                d[mt][nt][2] = bias0[nt];
                d[mt][nt][3] = bias1[nt];
            }

        const uint32_t baseH = uAH[p], baseL = uAL[p];
        uint32_t ah[2][4], al[2][4], bh[2], bl[2];
#pragma unroll
        for (int k0 = 0; k0 < 8; k0++) {
            const uint32_t ka = (uint32_t)(k0 * 32);
#pragma unroll
            for (int mt = 0; mt < 2; mt++) {
                ldsm_x4(ah[mt], baseH + aoff[mt] + ka);
                ldsm_x4(al[mt], baseL + aoff[mt] + ka);
            }
            const uint32_t kb = (uint32_t)(k0 * kstep);
#pragma unroll
            for (int nt = 0; nt < 8; nt++) {
                ldsm_x2t(bh, uBhi + boff + kb + nt * 16);
                ldsm_x2t(bl, uBlo + boff + kb + nt * 16);
#pragma unroll
                for (int mt = 0; mt < 2; mt++) {
                    mma_bf16(d[mt][nt], ah[mt], bh);
                    mma_bf16(d[mt][nt], ah[mt], bl);
                    mma_bf16(d[mt][nt], al[mt], bh);
                }
            }
        }

        // ---- build NEXT tile into buf 1-p (overlaps tensor/epilogue) ----
        if (g + NBLK_G < NTILE) buildA(aH[p ^ 1], aL[p ^ 1], g + NBLK_G, tid, sW1);

        // ---- register epilogue: masked relu-max over rows, shfl-reduce ----
        const bool m0 = g4      < sc;
        const bool m1 = g4 + 8  < sc;
        const bool m2 = g4 + 16 < sc;
        const bool m3 = g4 + 24 < sc;
        const int tO = (g * TPT + wm) * HH + nB;
#pragma unroll
        for (int nt = 0; nt < 8; nt++) {
            float v0 = 0.f, v1 = 0.f;   // 0-floor == relu + mask + empty case
            if (m0) { v0 = fmaxf(v0, d[0][nt][0]); v1 = fmaxf(v1, d[0][nt][1]); }
            if (m1) { v0 = fmaxf(v0, d[0][nt][2]); v1 = fmaxf(v1, d[0][nt][3]); }
            if (m2) { v0 = fmaxf(v0, d[1][nt][0]); v1 = fmaxf(v1, d[1][nt][1]); }
            if (m3) { v0 = fmaxf(v0, d[1][nt][2]); v1 = fmaxf(v1, d[1][nt][3]); }
#pragma unroll
            for (int o = 4; o < 32; o <<= 1) {
                v0 = fmaxf(v0, __shfl_xor_sync(0xffffffffu, v0, o));
                v1 = fmaxf(v1, __shfl_xor_sync(0xffffffffu, v1, o));
            }
            if (lane < 4)
                *(float2*)(out + tO + nt * 8 + lane * 2) = make_float2(v0, v1);
        }

        __syncthreads();   // buf p reads done; buf 1-p writes visible
        p ^= 1;
    }

    // ---- reset bin counters for the next graph replay (replaces k_zero) ----
    if (blockIdx.x == 0) {
        for (int i = tid; i < NCELL; i += 256) { g_cnt[i] = 0; g_fill[i] = 0; }
    }
}

// ---------------------------------------------------------------------------
__global__ void k_tail(const float* __restrict__ tpos, const int* __restrict__ tb,
                       float* __restrict__ out, int mode)
{
    int i = blockIdx.x * blockDim.x + threadIdx.x;
    const int off = N_TGT * HH;
    if (i < N_TGT * 3) out[off + i] = tpos[i];
    if (mode >= 2 && i < N_TGT) out[off + N_TGT * 3 + i] = (float)tb[i];
}

// ---------------------------------------------------------------------------
extern "C" void kernel_launch(void* const* d_in, const int* in_sizes, int n_in,
                              void* d_out, int out_size)
{
    const float* srcf = (const float*)d_in[0];
    const float* srcp = (const float*)d_in[1];
    const int*   srcb = (const int*)d_in[2];
    const float* tpos = (const float*)d_in[4];
    const int*   tbat = (const int*)d_in[5];
    const float* W1   = (const float*)d_in[6];
    const float* b1   = (const float*)d_in[7];
    const float* W2   = (const float*)d_in[8];
    const float* b2   = (const float*)d_in[9];
    float* out = (float*)d_out;

    cudaFuncSetAttribute(k_gemm, cudaFuncAttributeMaxDynamicSharedMemorySize, SMEM_G);

    k_pre<<<N_SRC / 4, 128>>>(srcf, srcp, srcb, W1, b1);
    k_scan<<<1, NCELL>>>();
    k_scatter<<<N_SRC / 128, 128>>>();
    k_search<<<N_TGT, 128>>>(tpos);
    k_gemm<<<NBLK_G, 256, SMEM_G>>>(W1, W2, b2, out);

    const int base = N_TGT * HH;
    if (out_size >= base + N_TGT * 3) {
        int mode = (out_size >= base + N_TGT * 3 + N_TGT) ? 2 : 1;
        int tot = N_TGT * 3;
        k_tail<<<(tot + 255) / 256, 256>>>(tpos, tbat, out, mode);
    }
}

// round 13
// speedup vs baseline: 1.4131x; 1.4131x over previous
#include <cuda_runtime.h>
#include <cuda_bf16.h>
#include <cstdint>

#define N_SRC 8192
#define N_TGT 16384
#define DD 64
#define HH 128
#define KN 32
#define CMAX 256
#define GRID 8
#define NCELL (GRID*GRID*GRID)
#define TPT 8                      // targets per GEMM tile (M = 256)
#define NTILE (N_TGT / TPT)        // 2048 tiles
#define NBLK_G 148                 // persistent GEMM blocks (1/SM)

#define LDA 136                    // bf16 leading dim (conflict-free ldmatrix)

// ---------------- device scratch ----------------
static __device__ float  g_S[N_SRC * HH];
static __device__ float4 g_spos[N_SRC];
static __device__ float  g_ss[N_SRC];
static __device__ int    g_cell[N_SRC];
static __device__ int    g_cnt[NCELL];          // zero-init; reset by k_gemm tail
static __device__ int    g_fill[NCELL];
static __device__ int    g_start[NCELL + 1];
static __device__ float4 g_bp[N_SRC];
static __device__ int    g_bidx[N_SRC];
static __device__ float4 g_nbr[N_TGT * KN];     // (relx, rely, relz, bitcast j or -1)
static __device__ int    g_scnt[N_TGT];

// ---------------- k_gemm smem layout (bytes) ----------------
#define SM_BHI   0                       // 128*136*2 = 34816
#define SM_BLO   34816
#define SM_AHI   69632                   // 256*136*2 = 69632
#define SM_ALO   139264
#define SM_W1    208896                  // 3*128*4 = 1536
#define SM_B2    210432                  // 512
#define SMEM_G   210944

static __device__ __forceinline__ uint32_t smem_u32(const void* p) {
    uint32_t a;
    asm("{ .reg .u64 t; cvta.to.shared.u64 t, %1; cvt.u32.u64 %0, t; }" : "=r"(a) : "l"(p));
    return a;
}

static __device__ __forceinline__ void ldsm_x4(uint32_t* r, uint32_t addr) {
    asm volatile("ldmatrix.sync.aligned.m8n8.x4.shared.b16 {%0,%1,%2,%3}, [%4];"
                 : "=r"(r[0]), "=r"(r[1]), "=r"(r[2]), "=r"(r[3]) : "r"(addr));
}
static __device__ __forceinline__ void ldsm_x2t(uint32_t* r, uint32_t addr) {
    asm volatile("ldmatrix.sync.aligned.m8n8.x2.trans.shared.b16 {%0,%1}, [%2];"
                 : "=r"(r[0]), "=r"(r[1]) : "r"(addr));
}
static __device__ __forceinline__ void mma_bf16(float* d, const uint32_t* a, const uint32_t* b) {
    asm volatile("mma.sync.aligned.m16n8k16.row.col.f32.bf16.bf16.f32 "
                 "{%0,%1,%2,%3}, {%4,%5,%6,%7}, {%8,%9}, {%0,%1,%2,%3};"
                 : "+f"(d[0]), "+f"(d[1]), "+f"(d[2]), "+f"(d[3])
                 : "r"(a[0]), "r"(a[1]), "r"(a[2]), "r"(a[3]), "r"(b[0]), "r"(b[1]));
}

static __device__ __forceinline__ int cell_of(float x, float y, float z) {
    int cx = min(GRID - 1, max(0, (int)floorf(x * (float)GRID)));
    int cy = min(GRID - 1, max(0, (int)floorf(y * (float)GRID)));
    int cz = min(GRID - 1, max(0, (int)floorf(z * (float)GRID)));
    return (cz * GRID + cy) * GRID + cx;
}

// ---------------------------------------------------------------------------
__global__ void __launch_bounds__(128) k_pre(
    const float* __restrict__ srcf, const float* __restrict__ srcp,
    const int* __restrict__ srcb, const float* __restrict__ W1,
    const float* __restrict__ b1)
{
    const int j0 = blockIdx.x * 4;
    const int t = threadIdx.x;
    __shared__ float sx[4][DD];
    for (int i = t; i < 4 * DD; i += 128) sx[i / DD][i % DD] = srcf[j0 * DD + i];
    __syncthreads();
    float a0, a1, a2, a3;
    a0 = a1 = a2 = a3 = b1[t];
#pragma unroll
    for (int d = 0; d < DD; d++) {
        float w = W1[d * HH + t];
        a0 = fmaf(sx[0][d], w, a0);
        a1 = fmaf(sx[1][d], w, a1);
        a2 = fmaf(sx[2][d], w, a2);
        a3 = fmaf(sx[3][d], w, a3);
    }
    g_S[(j0 + 0) * HH + t] = a0;
    g_S[(j0 + 1) * HH + t] = a1;
    g_S[(j0 + 2) * HH + t] = a2;
    g_S[(j0 + 3) * HH + t] = a3;
    if (t < 4) {
        int j = j0 + t;
        float x = srcp[j * 3 + 0], y = srcp[j * 3 + 1], z = srcp[j * 3 + 2];
        g_spos[j] = make_float4(x, y, z, (float)srcb[j]);
        g_ss[j] = x * x + y * y + z * z;
        int c = cell_of(x, y, z);
        g_cell[j] = c;
        atomicAdd(&g_cnt[c], 1);
    }
}

__global__ void __launch_bounds__(NCELL) k_scan() {
    __shared__ int s[NCELL];
    int t = threadIdx.x;
    s[t] = g_cnt[t];
    __syncthreads();
#pragma unroll
    for (int off = 1; off < NCELL; off <<= 1) {
        int v = (t >= off) ? s[t - off] : 0;
        __syncthreads();
        s[t] += v;
        __syncthreads();
    }
    g_start[t + 1] = s[t];
    if (t == 0) g_start[0] = 0;
}

__global__ void __launch_bounds__(128) k_scatter() {
    int j = blockIdx.x * 128 + threadIdx.x;
    if (j >= N_SRC) return;
    int c = g_cell[j];
    int off = atomicAdd(&g_fill[c], 1);
    int dst = g_start[c] + off;
    float4 p = g_spos[j];
    g_bp[dst] = make_float4(p.x, p.y, p.z, g_ss[j]);
    g_bidx[dst] = j;
}

// ---------------------------------------------------------------------------
// search: one block per target; warp-per-span scan + aggregated push
// ---------------------------------------------------------------------------
__global__ void __launch_bounds__(128) k_search(const float* __restrict__ tpos)
{
    __shared__ float cd2[CMAX];
    __shared__ int   cidx[CMAX];
    __shared__ int   ssel[KN];
    __shared__ int   scnt;

    const int t    = blockIdx.x;
    const int tid  = threadIdx.x;
    const int wid  = tid >> 5;
    const int lane = tid & 31;

    const float tx = tpos[t * 3 + 0];
    const float ty = tpos[t * 3 + 1];
    const float tz = tpos[t * 3 + 2];
    const float tt = tx * tx + ty * ty + tz * tz;
    const float R2 = (float)(0.12 * 0.12);

    if (tid == 0) scnt = 0;

    const float RM = 0.121f;
    const int lx = max(0, (int)floorf((tx - RM) * (float)GRID));
    const int hx = min(GRID - 1, (int)floorf((tx + RM) * (float)GRID));
    const int ly = max(0, (int)floorf((ty - RM) * (float)GRID));
    const int hy = min(GRID - 1, (int)floorf((ty + RM) * (float)GRID));
    const int lz = max(0, (int)floorf((tz - RM) * (float)GRID));
    const int hz = min(GRID - 1, (int)floorf((tz + RM) * (float)GRID));
    const int nsy = hy - ly + 1;
    const int ns  = nsy * (hz - lz + 1);
    __syncthreads();               // scnt visible

    for (int sp = wid; sp < ns; sp += 4) {
        const int cz = lz + sp / nsy;
        const int cy = ly + sp % nsy;
        const int cbase = (cz * GRID + cy) * GRID;
        const int s0 = g_start[cbase + lx];
        const int s1 = g_start[cbase + hx + 1];
        for (int s = s0 + lane; s - lane < s1; s += 32) {   // warp-uniform trip
            bool hit = false;
            float d2 = 0.f;
            if (s < s1) {
                float4 p = g_bp[s];
                float dot = tx * p.x + ty * p.y + tz * p.z;
                d2 = (tt + p.w) - 2.0f * dot;
                hit = (d2 <= R2);
            }
            unsigned m = __ballot_sync(0xffffffffu, hit);
            if (m) {
                int leader = __ffs(m) - 1;
                int base = 0;
                if (lane == leader) base = atomicAdd(&scnt, __popc(m));
                base = __shfl_sync(0xffffffffu, base, leader);
                if (hit) {
                    int off = base + __popc(m & ((1u << lane) - 1u));
                    if (off < CMAX) { cd2[off] = d2; cidx[off] = g_bidx[s]; }
                }
            }
        }
    }
    __syncthreads();

    const int C = min(scnt, CMAX);
    const int selCnt = min(C, KN);

    if (C <= KN) {
        if (tid < C) ssel[tid] = cidx[tid];
    } else {
        for (int i = tid; i < C; i += 128) {
            float di = cd2[i];
            int   ii = cidx[i];
            int r = 0;
            for (int k2 = 0; k2 < C; k2++) {
                float dk = cd2[k2];
                r += (int)((dk < di) || (dk == di && cidx[k2] < ii));
            }
            if (r < KN) ssel[r] = cidx[i];
        }
    }
    __syncthreads();

    if (tid < KN) {
        if (tid < selCnt) {
            int j = ssel[tid];
            float4 p = g_spos[j];
            g_nbr[t * KN + tid] = make_float4(p.x - tx, p.y - ty, p.z - tz,
                                              __int_as_float(j));
        } else {
            g_nbr[t * KN + tid] = make_float4(0.f, 0.f, 0.f, __int_as_float(-1));
        }
    }
    if (tid == 0) g_scnt[t] = selCnt;
}

// ---------------------------------------------------------------------------
// GEMM: persistent; per tile 8 targets x 32 nbrs (M=256); split-bf16 mma.sync
// A-build: warp-cooperative rows (8-lane groups) -> coalesced g_S reads
// ---------------------------------------------------------------------------
__global__ void __launch_bounds__(256) k_gemm(
    const float* __restrict__ W1, const float* __restrict__ W2g,
    const float* __restrict__ b2, float* __restrict__ out)
{
    extern __shared__ char smg[];
    __nv_bfloat16* sBhi = (__nv_bfloat16*)(smg + SM_BHI);
    __nv_bfloat16* sBlo = (__nv_bfloat16*)(smg + SM_BLO);
    __nv_bfloat16* sAhi = (__nv_bfloat16*)(smg + SM_AHI);
    __nv_bfloat16* sAlo = (__nv_bfloat16*)(smg + SM_ALO);
    float*         sW1  = (float*)(smg + SM_W1);      // [3][128]
    float*         sB2  = (float*)(smg + SM_B2);

    const int tid  = threadIdx.x;
    const int wid  = tid >> 5;
    const int lane = tid & 31;

    // ---- stage W2 split-bf16 (row-major [k][n]) + W1 positional rows + b2 ----
    for (int i = tid; i < HH * HH; i += 256) {
        int k = i >> 7, n = i & 127;
        float w = W2g[i];
        __nv_bfloat16 hb = __float2bfloat16(w);
        __nv_bfloat16 lb = __float2bfloat16(w - __bfloat162float(hb));
        sBhi[k * LDA + n] = hb;
        sBlo[k * LDA + n] = lb;
    }
    for (int i = tid; i < 3 * HH; i += 256) sW1[i] = W1[64 * HH + i];
    for (int i = tid; i < HH; i += 256)     sB2[i] = b2[i];
    __syncthreads();

    // warp tiling: 4m x 2n; warp tile 64 rows (2 targets) x 64 cols
    const int wm = wid & 3;
    const int wn = wid >> 2;
    const int mA = 64 * wm;
    const int nB = 64 * wn;

    const uint32_t uAhi = smem_u32(sAhi), uAlo = smem_u32(sAlo);
    const uint32_t uBhi = smem_u32(sBhi), uBlo = smem_u32(sBlo);

    // per-thread ldmatrix offsets (bytes)
    const int l15 = lane & 15;
    uint32_t aoff[4];
#pragma unroll
    for (int mt = 0; mt < 4; mt++)
        aoff[mt] = (uint32_t)(((mA + mt * 16 + l15) * LDA + (lane >> 4) * 8) * 2);
    const uint32_t boff  = (uint32_t)((l15 * LDA + nB) * 2);
    const uint32_t kstep = 16 * LDA * 2;

    // per-thread bias registers (cols fixed across tiles)
    const int tid4 = lane & 3;
    const int g4   = lane >> 2;
    float bias0[8], bias1[8];
#pragma unroll
    for (int nt = 0; nt < 8; nt++) {
        int c = nB + nt * 8 + tid4 * 2;
        bias0[nt] = sB2[c];
        bias1[nt] = sB2[c + 1];
    }

    // A-build cooperative indexing: 8-lane group per row, 4 rows per warp-pass
    const int lg   = lane & 7;          // lane within group
    const int grp  = lane >> 3;         // group (0..3) -> row within pass

    for (int g = blockIdx.x; g < NTILE; g += NBLK_G) {
        const int t0 = g * TPT;
        const int gbase = t0 * KN;

        const int sc0 = g_scnt[t0 + 2 * wm];
        const int sc1 = g_scnt[t0 + 2 * wm + 1];

        // ---- build A (h1) split-bf16, coalesced: 32 rows per pass ----
#pragma unroll
        for (int pass = 0; pass < 8; pass++) {
            const int row = pass * 32 + wid * 4 + grp;
            float4 nb = g_nbr[gbase + row];
            int j = __float_as_int(nb.w);
            const float* Srow = g_S + (j >= 0 ? j : 0) * HH;
            __nv_bfloat16* dh = sAhi + row * LDA;
            __nv_bfloat16* dl = sAlo + row * LDA;
#pragma unroll
            for (int q = 0; q < 4; q++) {
                const int col = lg * 4 + q * 32;
                float4 sv = (j >= 0) ? *(const float4*)(Srow + col)
                                     : make_float4(0.f, 0.f, 0.f, 0.f);
                float4 wx = *(const float4*)(sW1 + 0 * HH + col);
                float4 wy = *(const float4*)(sW1 + 1 * HH + col);
                float4 wz = *(const float4*)(sW1 + 2 * HH + col);
                float v0 = fmaxf(sv.x + nb.x * wx.x + nb.y * wy.x + nb.z * wz.x, 0.f);
                float v1 = fmaxf(sv.y + nb.x * wx.y + nb.y * wy.y + nb.z * wz.y, 0.f);
                float v2 = fmaxf(sv.z + nb.x * wx.z + nb.y * wy.z + nb.z * wz.z, 0.f);
                float v3 = fmaxf(sv.w + nb.x * wx.w + nb.y * wy.w + nb.z * wz.w, 0.f);
                __nv_bfloat162 h01 = __floats2bfloat162_rn(v0, v1);
                __nv_bfloat162 h23 = __floats2bfloat162_rn(v2, v3);
                __nv_bfloat162 l01 = __floats2bfloat162_rn(v0 - __low2float(h01),
                                                           v1 - __high2float(h01));
                __nv_bfloat162 l23 = __floats2bfloat162_rn(v2 - __low2float(h23),
                                                           v3 - __high2float(h23));
                *(uint2*)(dh + col) = make_uint2(*(uint32_t*)&h01, *(uint32_t*)&h23);
                *(uint2*)(dl + col) = make_uint2(*(uint32_t*)&l01, *(uint32_t*)&l23);
            }
        }
        __syncthreads();

        // ---- mma: D = bias + Ah*Bh + Ah*Bl + Al*Bh ----
        float d[4][8][4];
#pragma unroll
        for (int mt = 0; mt < 4; mt++)
#pragma unroll
            for (int nt = 0; nt < 8; nt++) {
                d[mt][nt][0] = bias0[nt];
                d[mt][nt][1] = bias1[nt];
                d[mt][nt][2] = bias0[nt];
                d[mt][nt][3] = bias1[nt];
            }

        uint32_t ah[4][4], al[4][4], bh[2], bl[2];
#pragma unroll
        for (int k0 = 0; k0 < 8; k0++) {
            const uint32_t ka = (uint32_t)(k0 * 32);
#pragma unroll
            for (int mt = 0; mt < 4; mt++) {
                ldsm_x4(ah[mt], uAhi + aoff[mt] + ka);
                ldsm_x4(al[mt], uAlo + aoff[mt] + ka);
            }
            const uint32_t kb = (uint32_t)(k0 * kstep);
#pragma unroll
            for (int nt = 0; nt < 8; nt++) {
                ldsm_x2t(bh, uBhi + boff + kb + nt * 16);
                ldsm_x2t(bl, uBlo + boff + kb + nt * 16);
#pragma unroll
                for (int mt = 0; mt < 4; mt++) {
                    mma_bf16(d[mt][nt], ah[mt], bh);
                    mma_bf16(d[mt][nt], ah[mt], bl);
                    mma_bf16(d[mt][nt], al[mt], bh);
                }
            }
        }
        __syncthreads();   // A reads done before next tile's A build

        // ---- register epilogue: 2 targets per warp ----
        const bool a0 = g4      < sc0, a1 = g4 + 8 < sc0;
        const bool a2 = g4 + 16 < sc0, a3 = g4 + 24 < sc0;
        const bool b0 = g4      < sc1, b1 = g4 + 8 < sc1;
        const bool b2m = g4 + 16 < sc1, b3 = g4 + 24 < sc1;
        const int tO0 = (t0 + 2 * wm) * HH + nB;
        const int tO1 = tO0 + HH;
#pragma unroll
        for (int nt = 0; nt < 8; nt++) {
            float v0 = 0.f, v1 = 0.f, w0 = 0.f, w1 = 0.f;
            if (a0) { v0 = fmaxf(v0, d[0][nt][0]); v1 = fmaxf(v1, d[0][nt][1]); }
            if (a1) { v0 = fmaxf(v0, d[0][nt][2]); v1 = fmaxf(v1, d[0][nt][3]); }
            if (a2) { v0 = fmaxf(v0, d[1][nt][0]); v1 = fmaxf(v1, d[1][nt][1]); }
            if (a3) { v0 = fmaxf(v0, d[1][nt][2]); v1 = fmaxf(v1, d[1][nt][3]); }
            if (b0) { w0 = fmaxf(w0, d[2][nt][0]); w1 = fmaxf(w1, d[2][nt][1]); }
            if (b1) { w0 = fmaxf(w0, d[2][nt][2]); w1 = fmaxf(w1, d[2][nt][3]); }
            if (b2m){ w0 = fmaxf(w0, d[3][nt][0]); w1 = fmaxf(w1, d[3][nt][1]); }
            if (b3) { w0 = fmaxf(w0, d[3][nt][2]); w1 = fmaxf(w1, d[3][nt][3]); }
#pragma unroll
            for (int o = 4; o < 32; o <<= 1) {
                v0 = fmaxf(v0, __shfl_xor_sync(0xffffffffu, v0, o));
                v1 = fmaxf(v1, __shfl_xor_sync(0xffffffffu, v1, o));
                w0 = fmaxf(w0, __shfl_xor_sync(0xffffffffu, w0, o));
                w1 = fmaxf(w1, __shfl_xor_sync(0xffffffffu, w1, o));
            }
            if (lane < 4) {
                *(float2*)(out + tO0 + nt * 8 + lane * 2) = make_float2(v0, v1);
                *(float2*)(out + tO1 + nt * 8 + lane * 2) = make_float2(w0, w1);
            }
        }
    }

    // ---- reset bin counters for the next graph replay (replaces k_zero) ----
    if (blockIdx.x == 0) {
        for (int i = tid; i < NCELL; i += 256) { g_cnt[i] = 0; g_fill[i] = 0; }
    }
}

// ---------------------------------------------------------------------------
__global__ void k_tail(const float* __restrict__ tpos, const int* __restrict__ tb,
                       float* __restrict__ out, int mode)
{
    int i = blockIdx.x * blockDim.x + threadIdx.x;
    const int off = N_TGT * HH;
    if (i < N_TGT * 3) out[off + i] = tpos[i];
    if (mode >= 2 && i < N_TGT) out[off + N_TGT * 3 + i] = (float)tb[i];
}

// ---------------------------------------------------------------------------
extern "C" void kernel_launch(void* const* d_in, const int* in_sizes, int n_in,
                              void* d_out, int out_size)
{
    const float* srcf = (const float*)d_in[0];
    const float* srcp = (const float*)d_in[1];
    const int*   srcb = (const int*)d_in[2];
    const float* tpos = (const float*)d_in[4];
    const int*   tbat = (const int*)d_in[5];
    const float* W1   = (const float*)d_in[6];
    const float* b1   = (const float*)d_in[7];
    const float* W2   = (const float*)d_in[8];
    const float* b2   = (const float*)d_in[9];
    float* out = (float*)d_out;

    cudaFuncSetAttribute(k_gemm, cudaFuncAttributeMaxDynamicSharedMemorySize, SMEM_G);

    k_pre<<<N_SRC / 4, 128>>>(srcf, srcp, srcb, W1, b1);
    k_scan<<<1, NCELL>>>();
    k_scatter<<<N_SRC / 128, 128>>>();
    k_search<<<N_TGT, 128>>>(tpos);
    k_gemm<<<NBLK_G, 256, SMEM_G>>>(W1, W2, b2, out);

    const int base = N_TGT * HH;
    if (out_size >= base + N_TGT * 3) {
        int mode = (out_size >= base + N_TGT * 3 + N_TGT) ? 2 : 1;
        int tot = N_TGT * 3;
        k_tail<<<(tot + 255) / 256, 256>>>(tpos, tbat, out, mode);
    }
}